// round 13
// baseline (speedup 1.0000x reference)
#include <cuda_runtime.h>
#include <math.h>
#include <stdint.h>

// Problem shape (fixed by the dataset instance)
#define BATCH 16
#define HEADS 8
#define HDIM  128
#define BSIZE 16               // tokens per cache block
#define BPS   128              // blocks per sequence
#define TMAX  (BSIZE * BPS)    // 2048 tokens
#define NSPLIT 8
#define TSPLIT (TMAX / NSPLIT)     // 256 tokens per split
#define BLKSPLIT (TSPLIT / BSIZE)  // 16 cache blocks per split
#define THREADS 256
#define NWARPS  (THREADS / 32)     // 8
#define STAGE_T 32                 // tokens per pipeline stage (16KB)
#define NSTAGE  (TSPLIT / STAGE_T) // 8 stages per phase

// split-KV partials + completion counters (allocation-free scratch, zero-init)
__device__ float g_part_o[BATCH * HEADS * NSPLIT * HDIM];
__device__ float g_part_m[BATCH * HEADS * NSPLIT];
__device__ float g_part_l[BATCH * HEADS * NSPLIT];
__device__ unsigned int g_cnt[BATCH * HEADS];

__device__ __forceinline__ float warp_sum(float v) {
#pragma unroll
    for (int o = 16; o > 0; o >>= 1) v += __shfl_xor_sync(0xffffffffu, v, o);
    return v;
}

// Prefetch one 32-token stage (16KB) into smem buffer via cp.async.cg.
// chunk c in [0,1024): token_in_stage = c>>5, float offset = (c&31)*4
__device__ __forceinline__ void prefetch_stage(
    float* sb, int s, int tbase, int tid, int h, int last,
    const int* s_bt, const float* cache, const float* fresh)
{
#pragma unroll
    for (int j = 0; j < 4; j++) {
        const int c   = j * THREADS + tid;
        const int tis = c >> 5;
        const int off = (c & 31) << 2;          // float offset
        const int lt  = s * STAGE_T + tis;
        const int t   = tbase + lt;
        const int blk = s_bt[lt >> 4];
        const size_t row = ((size_t)blk * BSIZE + (t & (BSIZE - 1))) * HEADS + h;
        const float* src = (t == last) ? (fresh + off)
                                       : (cache + row * HDIM + off);
        const uint32_t dst = (uint32_t)__cvta_generic_to_shared(
                                 sb + (size_t)tis * HDIM + off);
        asm volatile("cp.async.cg.shared.global [%0], [%1], 16;\n"
                     :: "r"(dst), "l"(src));
    }
    asm volatile("cp.async.commit_group;\n");
}

__global__ __launch_bounds__(THREADS)
void paged_attn_split_kernel(const float* __restrict__ q,
                             const float* __restrict__ knew,
                             const float* __restrict__ vnew,
                             const float* __restrict__ kcache,
                             const float* __restrict__ vcache,
                             const int*   __restrict__ block_tables,
                             const int*   __restrict__ context_lens,
                             float*       __restrict__ out)
{
    const float SCALE = 0.08838834764831845f;

    // Grid layout: adjacent CTAs = the 8 heads of the same (b, split) chunk.
    const int idx   = blockIdx.x;
    const int h     = idx % HEADS;
    const int bs_   = idx / HEADS;
    const int split = bs_ % NSPLIT;
    const int b     = bs_ / NSPLIT;
    const int bh    = b * HEADS + h;

    const int tid   = threadIdx.x;
    const int lane  = tid & 31;
    const int w     = tid >> 5;
    const int tbase = split * TSPLIT;

    __shared__ float s_buf[2][STAGE_T * HDIM];   // 2 x 16KB staging buffers
    __shared__ float s_scores[TSPLIT];
    __shared__ int   s_bt[BLKSPLIT];
    __shared__ float s_m[NWARPS];
    __shared__ float s_l[NWARPS];
    __shared__ float s_acc[NWARPS][HDIM];
    __shared__ unsigned int s_last;

    if (tid < BLKSPLIT)
        s_bt[tid] = block_tables[b * BPS + split * BLKSPLIT + tid];

    const int ctx  = context_lens[b];
    const int last = ctx - 1;

    float4 q4 = reinterpret_cast<const float4*>(q + (size_t)bh * HDIM)[lane];
    q4.x *= SCALE; q4.y *= SCALE; q4.z *= SCALE; q4.w *= SCALE;

    const float* kfresh = knew + (size_t)bh * HDIM;
    const float* vfresh = vnew + (size_t)bh * HDIM;

    __syncthreads();   // s_bt ready before first prefetch

    // ---- unified 16-unit pipeline: units 0..7 = K stages, 8..15 = V -------
    float  m   = -INFINITY;
    float  l   = 0.f;
    float4 acc = make_float4(0.f, 0.f, 0.f, 0.f);

    prefetch_stage(s_buf[0], 0, tbase, tid, h, last, s_bt, kcache, kfresh);

#pragma unroll 1
    for (int u = 0; u < 2 * NSTAGE; u++) {
        if (u + 1 < 2 * NSTAGE) {
            const int nu = u + 1;
            if (nu < NSTAGE)
                prefetch_stage(s_buf[nu & 1], nu, tbase, tid, h, last,
                               s_bt, kcache, kfresh);
            else
                prefetch_stage(s_buf[nu & 1], nu - NSTAGE, tbase, tid, h, last,
                               s_bt, vcache, vfresh);
            asm volatile("cp.async.wait_group 1;\n");
        } else {
            asm volatile("cp.async.wait_group 0;\n");
        }
        __syncthreads();

        const float* buf = s_buf[u & 1];
        if (u < NSTAGE) {
            // ---- K stage u: warp w handles tokens w*4 .. w*4+3 ------------
            const int s = u;
#pragma unroll
            for (int i = 0; i < 4; i++) {
                const int tis = w * 4 + i;
                const int lt  = s * STAGE_T + tis;
                const float4 kv =
                    reinterpret_cast<const float4*>(buf + (size_t)tis * HDIM)[lane];
                float sc = kv.x * q4.x + kv.y * q4.y + kv.z * q4.z + kv.w * q4.w;
                sc = warp_sum(sc);
                const float sv = (tbase + lt < ctx) ? sc : -INFINITY;
                m = fmaxf(m, sv);          // warp-uniform
                if (lane == i) s_scores[lt] = sv;
            }
        } else {
            if (u == NSTAGE) {
                // ---- per-warp softmax at the K->V boundary ----------------
                // warp w's 32 tokens are lt = s*32 + w*4 + i (s in 0..7,
                // i in 0..3). Lane e handles token (e>>2, e&3).
                __syncwarp();
                const int pos = (lane >> 2) * STAGE_T + w * 4 + (lane & 3);
                const float msafe = (m == -INFINITY) ? 0.0f : m;
                const float e = __expf(s_scores[pos] - msafe);
                s_scores[pos] = e;
                l = warp_sum(e);
                __syncwarp();
            }
            // ---- V stage u-8 ----------------------------------------------
            const int s = u - NSTAGE;
#pragma unroll
            for (int i = 0; i < 4; i++) {
                const int tis = w * 4 + i;
                const int lt  = s * STAGE_T + tis;
                const float p = s_scores[lt];
                const float4 vv =
                    reinterpret_cast<const float4*>(buf + (size_t)tis * HDIM)[lane];
                acc.x += p * vv.x;
                acc.y += p * vv.y;
                acc.z += p * vv.z;
                acc.w += p * vv.w;
            }
        }
        __syncthreads();   // stage consumed; its buffer may be overwritten
    }

    // ------------- cross-warp merge -> split partial ------------------------
    if (lane == 0) { s_m[w] = m; s_l[w] = l; }
    reinterpret_cast<float4*>(s_acc[w])[lane] = acc;
    __syncthreads();

    float M = -INFINITY;
#pragma unroll
    for (int ww = 0; ww < NWARPS; ww++) M = fmaxf(M, s_m[ww]);

    const int ps = bh * NSPLIT + split;
    if (tid < HDIM) {
        float r = 0.f;
#pragma unroll
        for (int ww = 0; ww < NWARPS; ww++) {
            const float coef = (s_m[ww] == -INFINITY) ? 0.f : __expf(s_m[ww] - M);
            r += coef * s_acc[ww][tid];
        }
        g_part_o[(size_t)ps * HDIM + tid] = r;
    }
    if (tid == 0) {
        float L = 0.f;
#pragma unroll
        for (int ww = 0; ww < NWARPS; ww++) {
            const float coef = (s_m[ww] == -INFINITY) ? 0.f : __expf(s_m[ww] - M);
            L += coef * s_l[ww];
        }
        g_part_m[ps] = M;
        g_part_l[ps] = L;
    }

    // ------------- last CTA per (b,h) combines (fused, no 2nd launch) ------
    __threadfence();
    __syncthreads();
    if (tid == 0)
        s_last = atomicAdd(&g_cnt[bh], 1u);
    __syncthreads();
    if (s_last != NSPLIT - 1) return;
    __threadfence();

    if (tid < HDIM) {
        float Mg = -INFINITY;
#pragma unroll
        for (int i = 0; i < NSPLIT; i++)
            Mg = fmaxf(Mg, g_part_m[bh * NSPLIT + i]);
        float Lg = 0.f, r = 0.f;
#pragma unroll
        for (int i = 0; i < NSPLIT; i++) {
            const float mi = g_part_m[bh * NSPLIT + i];
            const float coef = (mi == -INFINITY) ? 0.f : __expf(mi - Mg);
            Lg += coef * g_part_l[bh * NSPLIT + i];
            r  += coef * g_part_o[((size_t)bh * NSPLIT + i) * HDIM + tid];
        }
        out[(size_t)bh * HDIM + tid] = r / Lg;
    }
    if (tid == 0) g_cnt[bh] = 0;   // reset for next graph replay
}

extern "C" void kernel_launch(void* const* d_in, const int* in_sizes, int n_in,
                              void* d_out, int out_size)
{
    const float* q            = (const float*)d_in[0];
    const float* k            = (const float*)d_in[1];
    const float* v            = (const float*)d_in[2];
    const float* k_cache      = (const float*)d_in[3];
    const float* v_cache      = (const float*)d_in[4];
    // d_in[5] = slot_mapping (unused: substitution at t == ctx-1 is equivalent)
    const int*   block_tables = (const int*)d_in[6];
    const int*   context_lens = (const int*)d_in[7];
    float*       out          = (float*)d_out;

    paged_attn_split_kernel<<<BATCH * HEADS * NSPLIT, THREADS>>>(
        q, k, v, k_cache, v_cache, block_tables, context_lens, out);
}